// round 7
// baseline (speedup 1.0000x reference)
#include <cuda_runtime.h>
#include <cuda_bf16.h>

// RelativePositionEncoding (AF3-style), GB300 sm_103a — R7 (R6 + pack fix)
//
// out[i,j,:] = W_pos[dr] + W_tok[dt] + same_ent*w_ent + W_chain[dk]
// Fusions:
//   F[0..66)  = W_pos[r]  + W_tok[65]    (d_residue branch, !same_cr)
//   F[66..132)= W_pos[32] + W_tok[t]     (d_token branch,    same_cr)
//   C[dc]     = W_chain[k] + e*w_ent,  dc = e*6+k
//   D[dc]     = F[65] + C[dc]            (diff-chain fully fused row)
//
// f==65 <=> different chain -> out row = D[dc] (1 LDS); dc==5 additionally
// (diff entity) -> out row = D[5] cached in registers (0 LDS). Partition j's
// into 3 lists; 3 branch-free hot loops.
//
// R6 bug fixed: f needs 8 bits (max 130); C-list now packs j|f<<11|dc<<19.

#define N_TOK 1536
#define CZ 128
#define NTHREADS 768
#define NWARP (NTHREADS / 32)
#define TBL_FLOATS (156 * CZ)          // 132 F + 12 C + 12 D rows
#define OFF_A (TBL_FLOATS * 4)          // uint16[1536]
#define OFF_B (OFF_A + N_TOK * 2)       // uint16[1536]
#define OFF_C (OFF_B + N_TOK * 2)       // uint32[1536]
#define SMEM_BYTES (OFF_C + N_TOK * 4)  // 92160 B -> 2 CTAs/SM

__global__ __launch_bounds__(NTHREADS, 2)
void relpos_kernel(const int* __restrict__ asym,
                   const int* __restrict__ resi,
                   const int* __restrict__ enti,
                   const int* __restrict__ toki,
                   const int* __restrict__ symi,
                   const float* __restrict__ W,
                   float* __restrict__ out)
{
    extern __shared__ float sW[];
    unsigned short* sA = (unsigned short*)((char*)sW + OFF_A);
    unsigned short* sB = (unsigned short*)((char*)sW + OFF_B);
    unsigned*       sC = (unsigned*)((char*)sW + OFF_C);
    __shared__ int cnt[3];

    const int tid = threadIdx.x;
    const int i   = blockIdx.x;
    if (tid < 3) cnt[tid] = 0;

    // ---- Table build ----
    // W rows: [0,66)=pos, [66,132)=tok, 132=w_ent, [133,139)=chain
    #pragma unroll 4
    for (int idx = tid; idx < 132 * CZ; idx += NTHREADS) {
        const int row = idx >> 7;
        const int c   = idx & (CZ - 1);
        float v;
        if (row < 66) v = W[row * CZ + c] + W[131 * CZ + c];   // pos[row]+tok[65]
        else          v = W[32  * CZ + c] + W[row * CZ + c];   // pos[32]+tok[row-66]
        sW[idx] = v;
    }
    for (int idx = tid; idx < 12 * CZ; idx += NTHREADS) {
        const int row = idx >> 7;          // dc 0..11
        const int c   = idx & (CZ - 1);
        const int e   = row / 6;
        const int k   = row % 6;
        float cv = W[(133 + k) * CZ + c];
        if (e) cv += W[132 * CZ + c];
        sW[132 * CZ + idx] = cv;                                    // C[dc]
        sW[144 * CZ + idx] = cv + W[65 * CZ + c] + W[131 * CZ + c]; // D[dc]=F[65]+C[dc]
    }

    // ---- Partition j's into lists ----
    __syncthreads();
    const int ai = asym[i], ri = resi[i], ei = enti[i], ti = toki[i], si = symi[i];
    for (int j = tid; j < N_TOK; j += NTHREADS) {
        const int aj = __ldg(asym + j);
        const int rj = __ldg(resi + j);
        const int ej = __ldg(enti + j);
        const int tj = __ldg(toki + j);
        const int sj = __ldg(symi + j);

        const bool sc  = (ai == aj);
        const bool scr = sc && (ri == rj);
        int f;
        if (scr)      f = 66 + min(max(ti - tj + 32, 0), 64);   // 66..130
        else if (sc)  f = min(max(ri - rj + 32, 0), 64);        // 0..64
        else          f = 65;                                    // diff chain
        const bool se = (ei == ej);
        const int  dk = se ? min(max(si - sj + 2, 0), 4) : 5;
        const int  dc = (se ? 6 : 0) + dk;                       // 0..11

        if (f == 65) {
            if (dc == 5) { int p = atomicAdd(&cnt[0], 1); sA[p] = (unsigned short)j; }
            else         { int p = atomicAdd(&cnt[1], 1); sB[p] = (unsigned short)(j | (dc << 11)); }
        } else {
            int p = atomicAdd(&cnt[2], 1);
            // j:11 bits | f:8 bits | dc:4 bits  (f max 130 needs 8 bits!)
            sC[p] = (unsigned)j | ((unsigned)f << 11) | ((unsigned)dc << 19);
        }
    }
    __syncthreads();

    // ---- Hot loops ----
    const int lane = tid & 31;
    const int warp = tid >> 5;
    const float4* __restrict__ t4 = reinterpret_cast<const float4*>(sW);
    const float4* __restrict__ c4 = t4 + 132 * 32;
    const float4* __restrict__ d4 = t4 + 144 * 32;
    float4* __restrict__ obase =
        reinterpret_cast<float4*>(out) + (size_t)i * N_TOK * 32 + lane;

    const int nA = cnt[0], nB = cnt[1], nC = cnt[2];
    const float4 rA = d4[5 * 32 + lane];   // dominant row cached in registers

    // A: diff-chain, diff-entity — STG only.
    #pragma unroll 4
    for (int k = warp; k < nA; k += NWARP) {
        const int j = sA[k];
        __stcs(&obase[(size_t)j * 32], rA);
    }
    // B: diff-chain, same-entity — 1 LDS.128 + STG.
    #pragma unroll 2
    for (int k = warp; k < nB; k += NWARP) {
        const unsigned e = sB[k];
        const int j = e & 0x7FFu;
        const float4 r = d4[(e >> 11) * 32 + lane];
        __stcs(&obase[(size_t)j * 32], r);
    }
    // C: same-chain — 2 LDS.128 + add + STG.
    #pragma unroll 2
    for (int k = warp; k < nC; k += NWARP) {
        const unsigned e = sC[k];
        const int j  = e & 0x7FFu;
        const int f  = (e >> 11) & 0xFFu;
        const int dc = e >> 19;
        const float4 a = t4[f * 32 + lane];
        const float4 b = c4[dc * 32 + lane];
        float4 r;
        r.x = a.x + b.x; r.y = a.y + b.y; r.z = a.z + b.z; r.w = a.w + b.w;
        __stcs(&obase[(size_t)j * 32], r);
    }
}

extern "C" void kernel_launch(void* const* d_in, const int* in_sizes, int n_in,
                              void* d_out, int out_size)
{
    const int*   asym = (const int*)d_in[0];
    const int*   resi = (const int*)d_in[1];
    const int*   enti = (const int*)d_in[2];
    const int*   toki = (const int*)d_in[3];
    const int*   symi = (const int*)d_in[4];
    const float* W    = (const float*)d_in[5];
    float*       out  = (float*)d_out;

    cudaFuncSetAttribute(relpos_kernel,
                         cudaFuncAttributeMaxDynamicSharedMemorySize, SMEM_BYTES);

    relpos_kernel<<<N_TOK, NTHREADS, SMEM_BYTES>>>(asym, resi, enti, toki, symi, W, out);
}

// round 9
// speedup vs baseline: 1.0557x; 1.0557x over previous
#include <cuda_runtime.h>
#include <cuda_bf16.h>

// RelativePositionEncoding (AF3-style), GB300 sm_103a — R8
//
// out[i,j,:] = W_pos[dr] + W_tok[dt] + same_ent*w_ent + W_chain[dk]
// Fusions (proven since R2):
//   F[0..66)  = W_pos[r]  + W_tok[65]   (d_residue branch, !same_cr)
//   F[66..132)= W_pos[32] + W_tok[t]    (d_token branch,    same_cr)
//   C[e*6+k]  = W_chain[k] + e*w_ent
//
// R8 = R5 hot loop (sequential-j, 2xLDS.128 + 4 FADD + STG.128 streaming),
// made persistent:
//   456 CTAs x 512 thr (3/SM, 48 warps/SM), table built once per CTA.
//   Unit = half row (768 j's); 3072 units stolen via one global atomic per
//   unit (prefetched during index staging). 2 barriers per unit, ~6.7 units
//   per CTA -> sync cost ~0.1%. Tail idle ~ one unit. Counter reset by a
//   1-thread kernel launched first (same stream, graph-ordered).

#define N_TOK 1536
#define CZ 128
#define QJ 768                          // j's per unit (half row)
#define N_UNITS (N_TOK * 2)             // 3072
#define N_CTAS 456                      // 152 SMs * 3
#define NTHREADS 512
#define NWARP (NTHREADS / 32)
#define TBL_FLOATS (144 * CZ)
#define SMEM_BYTES (TBL_FLOATS * 4 + QJ * 2 + 16)

__device__ int g_ctr;

__global__ void reset_ctr() { g_ctr = 0; }

__global__ __launch_bounds__(NTHREADS, 3)
void relpos_kernel(const int* __restrict__ asym,
                   const int* __restrict__ resi,
                   const int* __restrict__ enti,
                   const int* __restrict__ toki,
                   const int* __restrict__ symi,
                   const float* __restrict__ W,
                   float* __restrict__ out)
{
    extern __shared__ float sW[];                              // [144][128]
    unsigned short* sIdx = (unsigned short*)(sW + TBL_FLOATS); // [QJ]
    int* sU = (int*)(sIdx + QJ);                               // stolen unit

    const int tid = threadIdx.x;

    // ---- One-time table build (per CTA) ----
    // W rows: [0,66)=pos, [66,132)=tok, 132=w_ent, [133,139)=chain
    #pragma unroll 4
    for (int idx = tid; idx < 132 * CZ; idx += NTHREADS) {
        const int row = idx >> 7;
        const int c   = idx & (CZ - 1);
        float v;
        if (row < 66) v = W[row * CZ + c] + W[131 * CZ + c];   // pos[row]+tok[65]
        else          v = W[32  * CZ + c] + W[row * CZ + c];   // pos[32]+tok[row-66]
        sW[idx] = v;
    }
    for (int idx = tid; idx < 12 * CZ; idx += NTHREADS) {
        const int row = idx >> 7;
        const int c   = idx & (CZ - 1);
        const int e   = row / 6;
        const int k   = row % 6;
        float v = W[(133 + k) * CZ + c];
        if (e) v += W[132 * CZ + c];
        sW[132 * CZ + idx] = v;
    }

    if (tid == 0) sU[0] = atomicAdd(&g_ctr, 1);
    __syncthreads();                    // table RAW + first unit visible
    int u = sU[0];

    const int lane = tid & 31;
    const int warp = tid >> 5;
    const float4* __restrict__ t4 = reinterpret_cast<const float4*>(sW);
    const float4* __restrict__ c4 = t4 + 132 * 32;
    float4* __restrict__ out4 = reinterpret_cast<float4*>(out);

    while (u < N_UNITS) {
        const int i  = u >> 1;
        const int jb = (u & 1) * QJ;

        // ---- Stage packed indices for this unit (all threads) ----
        const int ai = __ldg(asym + i);
        const int ri = __ldg(resi + i);
        const int ei = __ldg(enti + i);
        const int ti = __ldg(toki + i);
        const int si = __ldg(symi + i);

        #pragma unroll 2
        for (int t = tid; t < QJ; t += NTHREADS) {
            const int j  = jb + t;
            const int aj = __ldg(asym + j);
            const int rj = __ldg(resi + j);
            const int ej = __ldg(enti + j);
            const int tj = __ldg(toki + j);
            const int sj = __ldg(symi + j);

            const bool sc  = (ai == aj);
            const bool scr = sc && (ri == rj);
            int f;
            if (scr)      f = 66 + min(max(ti - tj + 32, 0), 64);
            else if (sc)  f = min(max(ri - rj + 32, 0), 64);
            else          f = 65;
            const bool se = (ei == ej);
            const int  dk = se ? min(max(si - sj + 2, 0), 4) : 5;
            const int  dc = (se ? 6 : 0) + dk;
            sIdx[t] = (unsigned short)(f | (dc << 8));
        }
        if (tid == 0) sU[0] = atomicAdd(&g_ctr, 1);   // prefetch next unit
        __syncthreads();                               // RAW: sIdx + sU ready

        // ---- Hot loop: 16 warps stride j within the unit, unroll x2 ----
        float4* __restrict__ o = out4 + ((size_t)i * N_TOK + jb) * 32 + lane;

        #pragma unroll 2
        for (int j = warp * 2; j < QJ; j += 32) {
            const unsigned p0 = sIdx[j];
            const unsigned p1 = sIdx[j + 1];

            const float4 a0 = t4[(p0 & 0xFFu) * 32 + lane];
            const float4 b0 = c4[(p0 >> 8)    * 32 + lane];
            const float4 a1 = t4[(p1 & 0xFFu) * 32 + lane];
            const float4 b1 = c4[(p1 >> 8)    * 32 + lane];

            float4 r0, r1;
            r0.x = a0.x + b0.x; r0.y = a0.y + b0.y; r0.z = a0.z + b0.z; r0.w = a0.w + b0.w;
            r1.x = a1.x + b1.x; r1.y = a1.y + b1.y; r1.z = a1.z + b1.z; r1.w = a1.w + b1.w;

            __stcs(&o[(size_t)j * 32],       r0);
            __stcs(&o[(size_t)(j + 1) * 32], r1);
        }

        const int nu = sU[0];
        __syncthreads();               // WAR: all reads of sIdx/sU done
        u = nu;
    }
}

extern "C" void kernel_launch(void* const* d_in, const int* in_sizes, int n_in,
                              void* d_out, int out_size)
{
    const int*   asym = (const int*)d_in[0];
    const int*   resi = (const int*)d_in[1];
    const int*   enti = (const int*)d_in[2];
    const int*   toki = (const int*)d_in[3];
    const int*   symi = (const int*)d_in[4];
    const float* W    = (const float*)d_in[5];
    float*       out  = (float*)d_out;

    cudaFuncSetAttribute(relpos_kernel,
                         cudaFuncAttributeMaxDynamicSharedMemorySize, SMEM_BYTES);

    reset_ctr<<<1, 1>>>();
    relpos_kernel<<<N_CTAS, NTHREADS, SMEM_BYTES>>>(asym, resi, enti, toki, symi, W, out);
}